// round 9
// baseline (speedup 1.0000x reference)
#include <cuda_runtime.h>
#include <cuda_bf16.h>

// ============================================================================
// LRML scoring, fused, k-permuted swizzled smem + LDS.128 operands.
// R9: 512 threads (16 warps -> 4/SMSP), CHUNK=64 (NSUB=4), warp owns <=3
//     n-frags so acc fits the 128-reg budget; Ls aliases dead A region;
//     register-prefetch pipeline for item loads.
//   logits[n,c] = item[n] . W[c]; columns:
//     c in [0,336): b*21+j -> u_b[d]*K[d,j] (j<20); j==20 -> u_b[d]
//     c in [336,356): mem_m[d] (IM);  [356,360) zero pad
//   score^2 = |u|^2 + |item|^2 - 2 u.item + 2 att.(UM - IM) + att^T G att
//
// Smem row = 128 floats. k-permutation: logical float4-chunk q=4p+tig holds
// k = 16p + tig + {0,4,8,12}. Physical chunk = 4*(p^(row&1)) + (tig^((p>>1)&3)).
// ============================================================================

#define D_DIM   128
#define M_DIM   20
#define B_USERS 16
#define C_USE   356
#define C_W     360
#define NFRAGS  45
#define THREADS 512
#define NWARP   16
#define CHUNK   64
#define NSUB    4
#define NJ      3
#define LSTRIDE 374
#define GRID    148

__device__ float g_UM[B_USERS * M_DIM];
__device__ float g_u2[B_USERS];
__device__ float g_G[M_DIM * M_DIM];

__device__ __forceinline__ unsigned f2tf32(float x) {
    unsigned r;
    asm("cvt.rna.tf32.f32 %0, %1;" : "=r"(r) : "f"(x));
    return r;
}
__device__ __forceinline__ float f2tf32f(float x) {
    return __uint_as_float(f2tf32(x));
}

__device__ __forceinline__ void mma_tf32(float* c, unsigned a0, unsigned a1,
                                         unsigned a2, unsigned a3,
                                         unsigned b0, unsigned b1) {
    asm volatile(
        "mma.sync.aligned.m16n8k8.row.col.f32.tf32.tf32.f32 "
        "{%0,%1,%2,%3}, {%4,%5,%6,%7}, {%8,%9}, {%0,%1,%2,%3};"
        : "+f"(c[0]), "+f"(c[1]), "+f"(c[2]), "+f"(c[3])
        : "r"(a0), "r"(a1), "r"(a2), "r"(a3), "r"(b0), "r"(b1));
}

__device__ __forceinline__ float2 ffma2(float2 a, float2 b, float2 c) {
    unsigned long long ra = *reinterpret_cast<unsigned long long*>(&a);
    unsigned long long rb = *reinterpret_cast<unsigned long long*>(&b);
    unsigned long long rc = *reinterpret_cast<unsigned long long*>(&c);
    unsigned long long rd;
    asm("fma.rn.f32x2 %0, %1, %2, %3;" : "=l"(rd) : "l"(ra), "l"(rb), "l"(rc));
    return *reinterpret_cast<float2*>(&rd);
}

// ids may be int64 or (silently downcast) int32 — sniff layout.
__device__ __forceinline__ void sniff_uids(const void* ids_raw, int* s_uid) {
    const long long* p64 = (const long long*)ids_raw;
    const int*       p32 = (const int*)ids_raw;
    bool is64 = true;
    for (int i = 0; i < 8; i++) {
        long long v = p64[i];
        if (v < 0 || v >= (1LL << 31)) is64 = false;
    }
    for (int i = 0; i < B_USERS; i++)
        s_uid[i] = is64 ? (int)p64[i] : p32[i];
}

// physical float index within a 128-float row for logical element d, row parity xb
__device__ __forceinline__ int swz_pos(int d, int xb) {
    int p = d >> 4, r16 = d & 15;
    int tig0 = r16 & 3, slot = r16 >> 2;
    int chunk = 4 * (p ^ xb) + (tig0 ^ ((p >> 1) & 3));
    return chunk * 4 + slot;
}

// ----------------------------------------------------------------------------
// pre2: UM, u2, G via one warp per 128-d dot product (736 dots).
// ----------------------------------------------------------------------------
__global__ void pre2_kernel(const float* __restrict__ users,
                            const float* __restrict__ mems,
                            const void*  __restrict__ ids_raw)
{
    __shared__ int s_uid[B_USERS];
    if (threadIdx.x == 0) sniff_uids(ids_raw, s_uid);
    __syncthreads();

    const int w = blockIdx.x * (blockDim.x >> 5) + (threadIdx.x >> 5);
    const int lane = threadIdx.x & 31;
    const int TOTAL = B_USERS * M_DIM + B_USERS + M_DIM * M_DIM;  // 736
    if (w >= TOTAL) return;

    const float4* pa;
    const float4* pb;
    float* dst;
    if (w < B_USERS * M_DIM) {
        int b = w / M_DIM, m = w % M_DIM;
        pa = (const float4*)(users + (size_t)s_uid[b] * D_DIM);
        pb = (const float4*)(mems + m * D_DIM);
        dst = &g_UM[w];
    } else if (w < B_USERS * M_DIM + B_USERS) {
        int b = w - B_USERS * M_DIM;
        pa = (const float4*)(users + (size_t)s_uid[b] * D_DIM);
        pb = pa;
        dst = &g_u2[b];
    } else {
        int t = w - B_USERS * M_DIM - B_USERS;
        pa = (const float4*)(mems + (t / M_DIM) * D_DIM);
        pb = (const float4*)(mems + (t % M_DIM) * D_DIM);
        dst = &g_G[t];
    }
    float4 a = pa[lane], b = pb[lane];
    float s = a.x * b.x + a.y * b.y + a.z * b.z + a.w * b.w;
#pragma unroll
    for (int o = 16; o; o >>= 1) s += __shfl_xor_sync(0xffffffffu, s, o);
    if (lane == 0) *dst = s;
}

// ----------------------------------------------------------------------------
// Fused GEMM + epilogue: 148 persistent CTAs, 16 warps, 64-item chunks.
// ----------------------------------------------------------------------------
__global__ void __launch_bounds__(THREADS, 1)
fused_kernel(const float* __restrict__ items,
             const float* __restrict__ users,
             const float* __restrict__ keyM,
             const float* __restrict__ mems,
             const void*  __restrict__ ids_raw,
             float* __restrict__ out, int N)
{
    extern __shared__ float smem[];
    float* Ws = smem;                         // [C_W][128] swizzled
    float* As = smem + C_W * 128;             // [CHUNK][128] swizzled
    float* Ls = As;                           // [16][LSTRIDE], aliases dead A

    __shared__ int s_uid[B_USERS];
    __shared__ float Gs[M_DIM * M_DIM];
    __shared__ float UMs[B_USERS * M_DIM];
    __shared__ float u2s[B_USERS];
    __shared__ float it2s[CHUNK];

    const int tid  = threadIdx.x;
    const int warp = tid >> 5;
    const int lane = tid & 31;
    const int g    = lane >> 2;
    const int tig  = lane & 3;

    if (tid == 0) sniff_uids(ids_raw, s_uid);
    for (int i = tid; i < M_DIM * M_DIM; i += THREADS) Gs[i] = g_G[i];
    for (int i = tid; i < B_USERS * M_DIM; i += THREADS) UMs[i] = g_UM[i];
    if (tid < B_USERS) u2s[tid] = g_u2[tid];
    __syncthreads();

    // Build W (tf32-rounded) into swizzled shared layout
    for (int idx = tid; idx < C_W * D_DIM; idx += THREADS) {
        int c = idx >> 7, d = idx & 127;
        float w = 0.f;
        if (c < B_USERS * 21) {
            int b = c / 21, j = c - b * 21;
            float u = users[(size_t)s_uid[b] * D_DIM + d];
            w = (j < M_DIM) ? u * keyM[d * M_DIM + j] : u;
        } else if (c < C_USE) {
            w = mems[(c - B_USERS * 21) * D_DIM + d];
        }
        Ws[c * 128 + swz_pos(d, c & 1)] = f2tf32f(w);
    }

    // Per-thread mainloop pointers (float4 units, rows of 32 float4s)
    const float4* pB[NJ];
#pragma unroll
    for (int j = 0; j < NJ; j++) {
        int f = warp + NWARP * j;
        if (f >= NFRAGS) f = 0;               // harmless duplicate, never dumped
        pB[j] = (const float4*)Ws + (f * 8 + g) * 32;
    }
    const float4* pA = (const float4*)As + g * 32;
    const int xb = g & 1;

    // staging identity: row r = tid>>3 (0..63), p-slot = tid&7 (one slot/thread)
    const int st_r = tid >> 3;
    const int st_p = tid & 7;
    const float4* itemsv = (const float4*)items;

    // ---- prefetch chunk 0 into registers ----
    float4 v0, v1, v2, v3;
    {
        int n = blockIdx.x * CHUNK + st_r;
        if (n < N) {
            const float4* src = itemsv + (size_t)n * 32 + 4 * st_p;
            v0 = src[0]; v1 = src[1]; v2 = src[2]; v3 = src[3];
        } else {
            v0 = v1 = v2 = v3 = make_float4(0.f, 0.f, 0.f, 0.f);
        }
    }
    __syncthreads();   // W build complete

    for (int base = blockIdx.x * CHUNK; base < N; base += GRID * CHUNK) {
        // ---- store prefetched regs -> As (tf32 round, swizzle), it2 ----
        {
            float s = v0.x*v0.x + v0.y*v0.y + v0.z*v0.z + v0.w*v0.w
                    + v1.x*v1.x + v1.y*v1.y + v1.z*v1.z + v1.w*v1.w
                    + v2.x*v2.x + v2.y*v2.y + v2.z*v2.z + v2.w*v2.w
                    + v3.x*v3.x + v3.y*v3.y + v3.z*v3.z + v3.w*v3.w;
#pragma unroll
            for (int o = 4; o; o >>= 1)
                s += __shfl_down_sync(0xffffffffu, s, o, 8);
            if (st_p == 0) it2s[st_r] = s;

            float4 t0 = v0, t1 = v1, t2 = v2, t3 = v3;
            t0.x=f2tf32f(t0.x); t0.y=f2tf32f(t0.y); t0.z=f2tf32f(t0.z); t0.w=f2tf32f(t0.w);
            t1.x=f2tf32f(t1.x); t1.y=f2tf32f(t1.y); t1.z=f2tf32f(t1.z); t1.w=f2tf32f(t1.w);
            t2.x=f2tf32f(t2.x); t2.y=f2tf32f(t2.y); t2.z=f2tf32f(t2.z); t2.w=f2tf32f(t2.w);
            t3.x=f2tf32f(t3.x); t3.y=f2tf32f(t3.y); t3.z=f2tf32f(t3.z); t3.w=f2tf32f(t3.w);

            int rxb = st_r & 1, sp = (st_p >> 1) & 3, cb = 4 * (st_p ^ rxb);
            float4* dst = (float4*)(As + st_r * 128);
            dst[cb + (0 ^ sp)] = make_float4(t0.x, t1.x, t2.x, t3.x);
            dst[cb + (1 ^ sp)] = make_float4(t0.y, t1.y, t2.y, t3.y);
            dst[cb + (2 ^ sp)] = make_float4(t0.z, t1.z, t2.z, t3.z);
            dst[cb + (3 ^ sp)] = make_float4(t0.w, t1.w, t2.w, t3.w);
        }
        __syncthreads();

        // ---- issue prefetch for next chunk (latency hides behind MMA) ----
        {
            int nb = base + GRID * CHUNK;
            if (nb < N) {
                int n = nb + st_r;
                if (n < N) {
                    const float4* src = itemsv + (size_t)n * 32 + 4 * st_p;
                    v0 = src[0]; v1 = src[1]; v2 = src[2]; v3 = src[3];
                } else {
                    v0 = v1 = v2 = v3 = make_float4(0.f, 0.f, 0.f, 0.f);
                }
            }
        }

        // ---- mma mainloop: 8 k-pairs x 4 subtiles x 3 frags ----
        float acc[NSUB][NJ][4];
#pragma unroll
        for (int s = 0; s < NSUB; s++)
#pragma unroll
            for (int j = 0; j < NJ; j++)
#pragma unroll
                for (int q = 0; q < 4; q++) acc[s][j][q] = 0.f;

#pragma unroll
        for (int p = 0; p < 8; p++) {
            const int o = 4 * (p ^ xb) + (tig ^ ((p >> 1) & 3));
            float4 b0 = pB[0][o], b1 = pB[1][o], b2 = pB[2][o];
#pragma unroll
            for (int s = 0; s < NSUB; s++) {
                float4 a0 = pA[s * 16 * 32 + o];
                float4 a1 = pA[(s * 16 + 8) * 32 + o];
                // kk = 2p: a = {a0.x, a1.x, a0.y, a1.y}
                mma_tf32(acc[s][0], __float_as_uint(a0.x), __float_as_uint(a1.x),
                                    __float_as_uint(a0.y), __float_as_uint(a1.y),
                                    __float_as_uint(b0.x), __float_as_uint(b0.y));
                mma_tf32(acc[s][1], __float_as_uint(a0.x), __float_as_uint(a1.x),
                                    __float_as_uint(a0.y), __float_as_uint(a1.y),
                                    __float_as_uint(b1.x), __float_as_uint(b1.y));
                mma_tf32(acc[s][2], __float_as_uint(a0.x), __float_as_uint(a1.x),
                                    __float_as_uint(a0.y), __float_as_uint(a1.y),
                                    __float_as_uint(b2.x), __float_as_uint(b2.y));
                // kk = 2p+1: a = {a0.z, a1.z, a0.w, a1.w}
                mma_tf32(acc[s][0], __float_as_uint(a0.z), __float_as_uint(a1.z),
                                    __float_as_uint(a0.w), __float_as_uint(a1.w),
                                    __float_as_uint(b0.z), __float_as_uint(b0.w));
                mma_tf32(acc[s][1], __float_as_uint(a0.z), __float_as_uint(a1.z),
                                    __float_as_uint(a0.w), __float_as_uint(a1.w),
                                    __float_as_uint(b1.z), __float_as_uint(b1.w));
                mma_tf32(acc[s][2], __float_as_uint(a0.z), __float_as_uint(a1.z),
                                    __float_as_uint(a0.w), __float_as_uint(a1.w),
                                    __float_as_uint(b2.z), __float_as_uint(b2.w));
            }
        }

        // ---- per-subtile: dump acc -> Ls (aliases As), then epilogue ----
#pragma unroll 1
        for (int s = 0; s < NSUB; s++) {
            __syncthreads();   // A reads (s=0) / prior epilogue reads complete
#pragma unroll
            for (int j = 0; j < NJ; j++) {
                int f = warp + NWARP * j;
                if (f < NFRAGS) {
                    int col = f * 8 + 2 * tig;
                    *(float2*)&Ls[g * LSTRIDE + col] =
                        make_float2(acc[s][j][0], acc[s][j][1]);
                    *(float2*)&Ls[(g + 8) * LSTRIDE + col] =
                        make_float2(acc[s][j][2], acc[s][j][3]);
                }
            }
            __syncthreads();

            if (tid < 256) {
                const int b  = tid >> 4;
                const int nl = tid & 15;
                const int n  = base + s * 16 + nl;
                if (n < N) {
                    const float* srow = &Ls[nl * LSTRIDE];
                    const float* lb = srow + b * 21;

                    float l[M_DIM];
#pragma unroll
                    for (int j = 0; j < M_DIM; j++) l[j] = lb[j];
                    float uit = lb[M_DIM];

                    float mx = l[0];
#pragma unroll
                    for (int j = 1; j < M_DIM; j++) mx = fmaxf(mx, l[j]);

                    float2 e2[M_DIM / 2];
                    float S = 0.f;
#pragma unroll
                    for (int j = 0; j < M_DIM / 2; j++) {
                        float ea = __expf(l[2 * j] - mx);
                        float eb = __expf(l[2 * j + 1] - mx);
                        e2[j] = make_float2(ea, eb);
                        S += ea + eb;
                    }

                    float2 acc1 = make_float2(0.f, 0.f);
#pragma unroll
                    for (int j = 0; j < M_DIM / 2; j++) {
                        float2 um = *(const float2*)&UMs[b * M_DIM + 2 * j];
                        float2 im = *(const float2*)&srow[B_USERS * 21 + 2 * j];
                        acc1 = ffma2(e2[j], make_float2(um.x - im.x, um.y - im.y), acc1);
                    }
                    float num1 = acc1.x + acc1.y;

                    float Q = 0.f;
#pragma unroll
                    for (int m2 = 0; m2 < M_DIM / 2; m2++) {
                        float2 qa = make_float2(0.f, 0.f);
                        float2 qb = make_float2(0.f, 0.f);
                        const float2* Gr0 = (const float2*)&Gs[(2 * m2) * M_DIM];
                        const float2* Gr1 = (const float2*)&Gs[(2 * m2 + 1) * M_DIM];
#pragma unroll
                        for (int j = 0; j < M_DIM / 2; j++) {
                            qa = ffma2(Gr0[j], e2[j], qa);
                            qb = ffma2(Gr1[j], e2[j], qb);
                        }
                        Q += e2[m2].x * (qa.x + qa.y) + e2[m2].y * (qb.x + qb.y);
                    }

                    float invS = 1.f / S;
                    float s2 = u2s[b] + it2s[s * 16 + nl] - 2.f * uit
                             + 2.f * num1 * invS + Q * invS * invS;
                    out[(size_t)b * N + n] = -sqrtf(fmaxf(s2, 0.f));
                }
            }
        }
        __syncthreads();   // it2s/Ls consumed before next store phase
    }
}

// ----------------------------------------------------------------------------
extern "C" void kernel_launch(void* const* d_in, const int* in_sizes, int n_in,
                              void* d_out, int out_size)
{
    const float* users = (const float*)d_in[0];
    const float* items = (const float*)d_in[1];
    const float* keyM  = (const float*)d_in[2];
    const float* mems  = (const float*)d_in[3];
    const void*  ids   = d_in[4];
    float* out = (float*)d_out;

    const int N = in_sizes[1] / D_DIM;

    const int smem_bytes = (C_W * 128 + CHUNK * 128) * 4;   // 217,088
    cudaFuncSetAttribute(fused_kernel,
                         cudaFuncAttributeMaxDynamicSharedMemorySize, smem_bytes);

    pre2_kernel<<<92, 256>>>(users, mems, ids);
    fused_kernel<<<GRID, THREADS, smem_bytes>>>(items, users, keyM, mems, ids, out, N);
}

// round 10
// speedup vs baseline: 1.4239x; 1.4239x over previous
#include <cuda_runtime.h>
#include <cuda_bf16.h>
#include <cstdint>

// ============================================================================
// LRML scoring, fused, bf16 m16n8k16 tensor-core GEMM:
//   logits[n,c] = item[n] . W[c]; columns:
//     c in [0,336): b*21+j -> u_b[d]*K[d,j] (j<20); j==20 -> u_b[d]
//     c in [336,356): mem_m[d] (IM);  [356,360) dead pad
//   score^2 = |u|^2 + |item|^2 - 2 u.item + 2 att.(UM - IM) + att^T G att
// R10: bf16 operands double FLOP per smem byte vs tf32.
//   W stored ONCE in B-fragment order: block(f,p) = 256B, thread lane owns
//     8B = [b0|b1] for col 8f+g, k 16p+{2tig,2tig+1, 8+2tig, 8+2tig+1}.
//   A stored row-major bf16 (row=256B), chunk-XOR swizzle phys=c^(r&7);
//     loaded with ldmatrix.m8n8.x4 (conflict-free).
// ============================================================================

#define D_DIM   128
#define M_DIM   20
#define B_USERS 16
#define C_USE   356
#define C_W     360
#define NFRAGS  45
#define CHUNK   32
#define NSUB    2
#define NJ      6
#define LSTRIDE 374
#define GRID    148

// smem byte offsets
#define WF_BYTES   (48 * 8 * 256)            // 98304
#define AS_OFF     WF_BYTES
#define AS_BYTES   (CHUNK * 256)             // 8192
#define LS_OFF     (AS_OFF + AS_BYTES)
#define LS_BYTES   (16 * LSTRIDE * 4)        // 23936
#define SMEM_TOTAL (LS_OFF + LS_BYTES)       // 130432

__device__ float g_UM[B_USERS * M_DIM];
__device__ float g_u2[B_USERS];
__device__ float g_G[M_DIM * M_DIM];

__device__ __forceinline__ uint32_t smem_u32(const void* p) {
    uint32_t a;
    asm("{ .reg .u64 t; cvta.to.shared.u64 t, %1; cvt.u32.u64 %0, t; }"
        : "=r"(a) : "l"(p));
    return a;
}
// pack two fp32 into bf16x2 (lo = first element)
__device__ __forceinline__ unsigned bf16pack(float lo, float hi) {
    unsigned r;
    asm("cvt.rn.bf16x2.f32 %0, %1, %2;" : "=r"(r) : "f"(hi), "f"(lo));
    return r;
}

__device__ __forceinline__ void mma_bf16(float* c, unsigned a0, unsigned a1,
                                         unsigned a2, unsigned a3,
                                         unsigned b0, unsigned b1) {
    asm volatile(
        "mma.sync.aligned.m16n8k16.row.col.f32.bf16.bf16.f32 "
        "{%0,%1,%2,%3}, {%4,%5,%6,%7}, {%8,%9}, {%0,%1,%2,%3};"
        : "+f"(c[0]), "+f"(c[1]), "+f"(c[2]), "+f"(c[3])
        : "r"(a0), "r"(a1), "r"(a2), "r"(a3), "r"(b0), "r"(b1));
}

__device__ __forceinline__ void ldmatrix4(unsigned* r, uint32_t addr) {
    asm volatile("ldmatrix.sync.aligned.m8n8.x4.shared.b16 {%0,%1,%2,%3}, [%4];"
                 : "=r"(r[0]), "=r"(r[1]), "=r"(r[2]), "=r"(r[3]) : "r"(addr));
}
__device__ __forceinline__ void lds64(unsigned& b0, unsigned& b1, uint32_t addr) {
    asm volatile("ld.shared.v2.u32 {%0,%1}, [%2];" : "=r"(b0), "=r"(b1) : "r"(addr));
}
__device__ __forceinline__ void sts128(uint32_t addr, unsigned w0, unsigned w1,
                                       unsigned w2, unsigned w3) {
    asm volatile("st.shared.v4.u32 [%0], {%1,%2,%3,%4};"
                 :: "r"(addr), "r"(w0), "r"(w1), "r"(w2), "r"(w3) : "memory");
}
__device__ __forceinline__ void sts32(uint32_t addr, unsigned w) {
    asm volatile("st.shared.u32 [%0], %1;" :: "r"(addr), "r"(w) : "memory");
}

__device__ __forceinline__ float2 ffma2(float2 a, float2 b, float2 c) {
    unsigned long long ra = *reinterpret_cast<unsigned long long*>(&a);
    unsigned long long rb = *reinterpret_cast<unsigned long long*>(&b);
    unsigned long long rc = *reinterpret_cast<unsigned long long*>(&c);
    unsigned long long rd;
    asm("fma.rn.f32x2 %0, %1, %2, %3;" : "=l"(rd) : "l"(ra), "l"(rb), "l"(rc));
    return *reinterpret_cast<float2*>(&rd);
}

// ids may be int64 or (silently downcast) int32 — sniff layout.
__device__ __forceinline__ void sniff_uids(const void* ids_raw, int* s_uid) {
    const long long* p64 = (const long long*)ids_raw;
    const int*       p32 = (const int*)ids_raw;
    bool is64 = true;
    for (int i = 0; i < 8; i++) {
        long long v = p64[i];
        if (v < 0 || v >= (1LL << 31)) is64 = false;
    }
    for (int i = 0; i < B_USERS; i++)
        s_uid[i] = is64 ? (int)p64[i] : p32[i];
}

// ----------------------------------------------------------------------------
// pre2: UM, u2, G via one warp per 128-d dot product (736 dots).
// ----------------------------------------------------------------------------
__global__ void pre2_kernel(const float* __restrict__ users,
                            const float* __restrict__ mems,
                            const void*  __restrict__ ids_raw)
{
    __shared__ int s_uid[B_USERS];
    if (threadIdx.x == 0) sniff_uids(ids_raw, s_uid);
    __syncthreads();

    const int w = blockIdx.x * (blockDim.x >> 5) + (threadIdx.x >> 5);
    const int lane = threadIdx.x & 31;
    const int TOTAL = B_USERS * M_DIM + B_USERS + M_DIM * M_DIM;  // 736
    if (w >= TOTAL) return;

    const float4* pa;
    const float4* pb;
    float* dst;
    if (w < B_USERS * M_DIM) {
        int b = w / M_DIM, m = w % M_DIM;
        pa = (const float4*)(users + (size_t)s_uid[b] * D_DIM);
        pb = (const float4*)(mems + m * D_DIM);
        dst = &g_UM[w];
    } else if (w < B_USERS * M_DIM + B_USERS) {
        int b = w - B_USERS * M_DIM;
        pa = (const float4*)(users + (size_t)s_uid[b] * D_DIM);
        pb = pa;
        dst = &g_u2[b];
    } else {
        int t = w - B_USERS * M_DIM - B_USERS;
        pa = (const float4*)(mems + (t / M_DIM) * D_DIM);
        pb = (const float4*)(mems + (t % M_DIM) * D_DIM);
        dst = &g_G[t];
    }
    float4 a = pa[lane], b = pb[lane];
    float s = a.x * b.x + a.y * b.y + a.z * b.z + a.w * b.w;
#pragma unroll
    for (int o = 16; o; o >>= 1) s += __shfl_xor_sync(0xffffffffu, s, o);
    if (lane == 0) *dst = s;
}

// ----------------------------------------------------------------------------
// Fused bf16 GEMM + epilogue: 148 persistent CTAs, 8 warps, 32-item chunks.
// ----------------------------------------------------------------------------
__global__ void __launch_bounds__(256, 1)
fused_kernel(const float* __restrict__ items,
             const float* __restrict__ users,
             const float* __restrict__ keyM,
             const float* __restrict__ mems,
             const void*  __restrict__ ids_raw,
             float* __restrict__ out, int N)
{
    extern __shared__ char smem_c[];
    float* Ls = (float*)(smem_c + LS_OFF);
    const uint32_t sbase = smem_u32(smem_c);
    const uint32_t Wb = sbase;
    const uint32_t Ab = sbase + AS_OFF;

    __shared__ int s_uid[B_USERS];
    __shared__ float Gs[M_DIM * M_DIM];
    __shared__ float UMs[B_USERS * M_DIM];
    __shared__ float u2s[B_USERS];
    __shared__ float it2s[CHUNK];

    const int tid  = threadIdx.x;
    const int warp = tid >> 5;
    const int lane = tid & 31;
    const int g    = lane >> 2;
    const int tig  = lane & 3;

    if (tid == 0) sniff_uids(ids_raw, s_uid);
    for (int i = tid; i < M_DIM * M_DIM; i += 256) Gs[i] = g_G[i];
    for (int i = tid; i < B_USERS * M_DIM; i += 256) UMs[i] = g_UM[i];
    if (tid < B_USERS) u2s[tid] = g_u2[tid];
    __syncthreads();

    // ---- build W (bf16) directly in B-fragment order ----
    // idx over (c, k-pair kp): k = 2kp, 2kp+1
    for (int idx = tid; idx < C_W * 64; idx += 256) {
        int c = idx >> 6, kp = idx & 63;
        float w0 = 0.f, w1 = 0.f;
        int k0 = 2 * kp;
        if (c < B_USERS * 21) {
            int b = c / 21, j = c - b * 21;
            float ua = users[(size_t)s_uid[b] * D_DIM + k0];
            float ub = users[(size_t)s_uid[b] * D_DIM + k0 + 1];
            if (j < M_DIM) {
                w0 = ua * keyM[k0 * M_DIM + j];
                w1 = ub * keyM[(k0 + 1) * M_DIM + j];
            } else { w0 = ua; w1 = ub; }
        } else if (c < C_USE) {
            w0 = mems[(c - B_USERS * 21) * D_DIM + k0];
            w1 = mems[(c - B_USERS * 21) * D_DIM + k0 + 1];
        }
        int f = c >> 3, gg = c & 7;
        int p = kp >> 3, tg = kp & 3, half = (kp >> 2) & 1;
        uint32_t addr = Wb + (uint32_t)((f * 8 + p) * 256 + (4 * gg + tg) * 8 + half * 4);
        sts32(addr, bf16pack(w0, w1));
    }

    // per-thread frag base addresses (B)
    uint32_t bjb[NJ];
#pragma unroll
    for (int j = 0; j < NJ; j++) {
        int f = warp + 8 * j;
        if (f >= NFRAGS) f = 0;              // harmless duplicate, never dumped
        bjb[j] = Wb + (uint32_t)(f * 2048 + lane * 8);
    }
    // ldmatrix per-lane bases (A)
    const int l15 = lane & 15, hi = lane >> 4, l7 = lane & 7;
    const uint32_t a_base0 = Ab + (uint32_t)(l15 * 256);
    const uint32_t a_base1 = a_base0 + 16 * 256;

    // staging identity: row r = tid>>3 (0..31), q = tid&7; chunks {q, q+8}
    const int st_r = tid >> 3;
    const int st_q = tid & 7;
    const uint32_t st_a1 = Ab + (uint32_t)(st_r * 256 + ((st_q) ^ (st_r & 7)) * 16);
    const uint32_t st_a2 = Ab + (uint32_t)(st_r * 256 + ((st_q + 8) ^ (st_r & 7)) * 16);
    const float4* itemsv = (const float4*)items;

    // ---- prefetch chunk 0 ----
    float4 v0, v1, v2, v3;
    {
        int n = blockIdx.x * CHUNK + st_r;
        if (n < N) {
            const float4* src = itemsv + (size_t)n * 32;
            v0 = src[2 * st_q]; v1 = src[2 * st_q + 1];
            v2 = src[16 + 2 * st_q]; v3 = src[17 + 2 * st_q];
        } else {
            v0 = v1 = v2 = v3 = make_float4(0.f, 0.f, 0.f, 0.f);
        }
    }
    __syncthreads();   // W build complete

    for (int base = blockIdx.x * CHUNK; base < N; base += GRID * CHUNK) {
        // ---- store staged regs -> As (bf16, swizzled), it2 ----
        {
            float s = v0.x*v0.x + v0.y*v0.y + v0.z*v0.z + v0.w*v0.w
                    + v1.x*v1.x + v1.y*v1.y + v1.z*v1.z + v1.w*v1.w
                    + v2.x*v2.x + v2.y*v2.y + v2.z*v2.z + v2.w*v2.w
                    + v3.x*v3.x + v3.y*v3.y + v3.z*v3.z + v3.w*v3.w;
#pragma unroll
            for (int o = 4; o; o >>= 1)
                s += __shfl_down_sync(0xffffffffu, s, o, 8);
            if (st_q == 0) it2s[st_r] = s;

            sts128(st_a1, bf16pack(v0.x, v0.y), bf16pack(v0.z, v0.w),
                          bf16pack(v1.x, v1.y), bf16pack(v1.z, v1.w));
            sts128(st_a2, bf16pack(v2.x, v2.y), bf16pack(v2.z, v2.w),
                          bf16pack(v3.x, v3.y), bf16pack(v3.z, v3.w));
        }
        __syncthreads();

        // ---- prefetch next chunk (hides behind MMA) ----
        {
            int nb = base + GRID * CHUNK;
            if (nb < N) {
                int n = nb + st_r;
                if (n < N) {
                    const float4* src = itemsv + (size_t)n * 32;
                    v0 = src[2 * st_q]; v1 = src[2 * st_q + 1];
                    v2 = src[16 + 2 * st_q]; v3 = src[17 + 2 * st_q];
                } else {
                    v0 = v1 = v2 = v3 = make_float4(0.f, 0.f, 0.f, 0.f);
                }
            }
        }

        // ---- mma mainloop: 8 k16-steps x 2 subtiles x 6 frags ----
        float acc[NSUB][NJ][4];
#pragma unroll
        for (int s = 0; s < NSUB; s++)
#pragma unroll
            for (int j = 0; j < NJ; j++)
#pragma unroll
                for (int q = 0; q < 4; q++) acc[s][j][q] = 0.f;

#pragma unroll
        for (int p = 0; p < 8; p++) {
            const uint32_t phys = (uint32_t)((((2 * p + hi) ^ l7)) << 4);
            unsigned a0[4], a1[4];
            ldmatrix4(a0, a_base0 + phys);
            ldmatrix4(a1, a_base1 + phys);
#pragma unroll
            for (int j = 0; j < NJ; j++) {
                unsigned b0, b1;
                lds64(b0, b1, bjb[j] + (uint32_t)(p * 256));
                mma_bf16(acc[0][j], a0[0], a0[1], a0[2], a0[3], b0, b1);
                mma_bf16(acc[1][j], a1[0], a1[1], a1[2], a1[3], b0, b1);
            }
        }

        // ---- per-subtile: dump acc -> Ls, then epilogue ----
#pragma unroll 1
        for (int s = 0; s < NSUB; s++) {
            if (s) __syncthreads();
#pragma unroll
            for (int j = 0; j < NJ; j++) {
                int f = warp + 8 * j;
                if (f < NFRAGS) {
                    int col = f * 8 + 2 * tig;
                    *(float2*)&Ls[g * LSTRIDE + col] =
                        make_float2(acc[s][j][0], acc[s][j][1]);
                    *(float2*)&Ls[(g + 8) * LSTRIDE + col] =
                        make_float2(acc[s][j][2], acc[s][j][3]);
                }
            }
            __syncthreads();

            const int b  = tid >> 4;
            const int nl = tid & 15;
            const int n  = base + s * 16 + nl;
            if (n < N) {
                const float* srow = &Ls[nl * LSTRIDE];
                const float* lb = srow + b * 21;

                float l[M_DIM];
#pragma unroll
                for (int j = 0; j < M_DIM; j++) l[j] = lb[j];
                float uit = lb[M_DIM];

                float mx = l[0];
#pragma unroll
                for (int j = 1; j < M_DIM; j++) mx = fmaxf(mx, l[j]);

                float2 e2[M_DIM / 2];
                float S = 0.f;
#pragma unroll
                for (int j = 0; j < M_DIM / 2; j++) {
                    float ea = __expf(l[2 * j] - mx);
                    float eb = __expf(l[2 * j + 1] - mx);
                    e2[j] = make_float2(ea, eb);
                    S += ea + eb;
                }

                float2 acc1 = make_float2(0.f, 0.f);
#pragma unroll
                for (int j = 0; j < M_DIM / 2; j++) {
                    float2 um = *(const float2*)&UMs[b * M_DIM + 2 * j];
                    float2 im = *(const float2*)&srow[B_USERS * 21 + 2 * j];
                    acc1 = ffma2(e2[j], make_float2(um.x - im.x, um.y - im.y), acc1);
                }
                float num1 = acc1.x + acc1.y;

                float Q = 0.f;
#pragma unroll
                for (int m2 = 0; m2 < M_DIM / 2; m2++) {
                    float2 qa = make_float2(0.f, 0.f);
                    float2 qb = make_float2(0.f, 0.f);
                    const float2* Gr0 = (const float2*)&Gs[(2 * m2) * M_DIM];
                    const float2* Gr1 = (const float2*)&Gs[(2 * m2 + 1) * M_DIM];
#pragma unroll
                    for (int j = 0; j < M_DIM / 2; j++) {
                        qa = ffma2(Gr0[j], e2[j], qa);
                        qb = ffma2(Gr1[j], e2[j], qb);
                    }
                    Q += e2[m2].x * (qa.x + qa.y) + e2[m2].y * (qb.x + qb.y);
                }

                float invS = 1.f / S;
                float s2 = u2s[b] + it2s[s * 16 + nl] - 2.f * uit
                         + 2.f * num1 * invS + Q * invS * invS;
                out[(size_t)b * N + n] = -sqrtf(fmaxf(s2, 0.f));
            }
        }
        __syncthreads();   // Ls/it2s/As consumed before next store phase
    }
}

// ----------------------------------------------------------------------------
extern "C" void kernel_launch(void* const* d_in, const int* in_sizes, int n_in,
                              void* d_out, int out_size)
{
    const float* users = (const float*)d_in[0];
    const float* items = (const float*)d_in[1];
    const float* keyM  = (const float*)d_in[2];
    const float* mems  = (const float*)d_in[3];
    const void*  ids   = d_in[4];
    float* out = (float*)d_out;

    const int N = in_sizes[1] / D_DIM;

    cudaFuncSetAttribute(fused_kernel,
                         cudaFuncAttributeMaxDynamicSharedMemorySize, SMEM_TOTAL);

    pre2_kernel<<<92, 256>>>(users, mems, ids);
    fused_kernel<<<GRID, 256, SMEM_TOTAL>>>(items, users, keyM, mems, ids, out, N);
}